// round 5
// baseline (speedup 1.0000x reference)
#include <cuda_runtime.h>
#include <math.h>

#define NB   2048
#define NTOK 176
#define NQ   128

// Scratch (allocation-free rule: device globals)
__device__ float g_KT[NB * 64 * NTOK];   // [b][d][k]
__device__ float g_V [NB * NTOK * 64];   // [b][k][d]
__device__ float g_QT[NB * 64 * NQ];     // [b][d][q]

#define SWZ(g, r) ((((g) ^ (r) ^ ((r) >> 3))) & 31)

// ---------------- packed f32x2 helpers (Blackwell FFMA2) -------------------
typedef unsigned long long u64t;
__device__ __forceinline__ void fma2(u64t& acc, u64t a, u64t b) {
    asm("fma.rn.f32x2 %0, %1, %2, %0;" : "+l"(acc) : "l"(a), "l"(b));
}
__device__ __forceinline__ u64t bc2(float x) {
    u64t r; unsigned int xi = __float_as_uint(x);
    asm("mov.b64 %0, {%1, %1};" : "=l"(r) : "r"(xi));
    return r;
}
__device__ __forceinline__ float2 up2(u64t v) {
    float2 r; asm("mov.b64 {%0, %1}, %2;" : "=f"(r.x), "=f"(r.y) : "l"(v));
    return r;
}

// ---------------------------------------------------------------------------
// Kernel 1: entity FFN encoders + K/V/Q projections.
// 2816 blocks x 256 threads; each block = 128 tokens of one entity type.
// Single weight buffer reloaded per phase (W2 -> WK -> WV -> WQ);
// H lives in the X buffer's first half. smem 53KB -> 3 CTAs/SM.
// ---------------------------------------------------------------------------
__global__ void __launch_bounds__(256, 3) encode_kernel(
    const float* __restrict__ pred_state, const float* __restrict__ prey_state,
    const float* __restrict__ obst_state, const float* __restrict__ emb,
    const float* __restrict__ p_w1, const float* __restrict__ p_b1,
    const float* __restrict__ p_w2, const float* __restrict__ p_b2,
    const float* __restrict__ y_w1, const float* __restrict__ y_b1,
    const float* __restrict__ y_w2, const float* __restrict__ y_b2,
    const float* __restrict__ o_w1, const float* __restrict__ o_b1,
    const float* __restrict__ o_w2, const float* __restrict__ o_b2,
    const float* __restrict__ wq, const float* __restrict__ bq,
    const float* __restrict__ wk, const float* __restrict__ bk,
    const float* __restrict__ wv, const float* __restrict__ bv)
{
    extern __shared__ float sm[];
    float* sW  = sm;            // 4096: W2, then WK, then WV, then WQ
    float* sX  = sm + 4096;     // 8192: H [32][128] in first half, then X [64][128] swz
    float* sC  = sm + 12288;    // 64
    float* sBK = sm + 12352;    // 64
    float* sBV = sm + 12416;    // 64
    float* sBQ = sm + 12480;    // 64
    float* sB1 = sm + 12544;    // 64
    float* sW1 = sm + 12608;    // 192
    float* sSt = sm + 12800;    // 384   (total 13184)

    const int tid = threadIdx.x;
    const int blk = blockIdx.x;

    int type, inDim, perShift, slotBase, tok0;
    const float *state, *w1, *b1, *w2;
    const float *b2;
    if (blk < 256)       { type = 0; tok0 = blk * 128;          state = pred_state; w1 = p_w1; b1 = p_b1; w2 = p_w2; b2 = p_b2; inDim = 2; perShift = 4; slotBase = 0;   }
    else if (blk < 2304) { type = 1; tok0 = (blk - 256)  * 128; state = prey_state; w1 = y_w1; b1 = y_b1; w2 = y_w2; b2 = y_b2; inDim = 2; perShift = 7; slotBase = 16;  }
    else                 { type = 2; tok0 = (blk - 2304) * 128; state = obst_state; w1 = o_w1; b1 = o_b1; w2 = o_w2; b2 = o_b2; inDim = 3; perShift = 5; slotBase = 144; }

    // phase 0: stage W2 + consts + states
    for (int i = tid; i < 4096; i += 256) sW[i] = w2[i];
    if (tid < 64) {
        sC[tid]  = b2[tid] + emb[type * 64 + tid];
        sBK[tid] = bk[tid];
        sBV[tid] = bv[tid];
        sBQ[tid] = bq[tid];
        sB1[tid] = b1[tid];
    }
    if (tid < inDim * 64) sW1[tid] = w1[tid];
    for (int i = tid; i < 128 * inDim; i += 256) {
        int t = i / inDim, j = i - t * inDim;
        sSt[t * 3 + j] = state[(tok0 + t) * inDim + j];
    }
    __syncthreads();

    const int dg = tid & 7, tg = tid >> 3, ds = dg * 8;

    // X = H @ W2 accumulated over two 32-k halves (H uses sX[0:4096])
    u64t accX[4][4];
#pragma unroll
    for (int i = 0; i < 4; i++)
#pragma unroll
        for (int j = 0; j < 4; j++) accX[i][j] = 0ULL;

#pragma unroll 1
    for (int h = 0; h < 2; h++) {
        for (int e = tid; e < 4096; e += 256) {
            int k = e >> 7, t = e & 127;
            int gk = h * 32 + k;
            float a = sB1[gk];
            for (int j = 0; j < inDim; j++) a += sSt[t * 3 + j] * sW1[j * 64 + gk];
            sX[k * 128 + t] = fmaxf(a, 0.f);
        }
        __syncthreads();
#pragma unroll 4
        for (int kk = 0; kk < 32; kk++) {
            float4 a4 = *(const float4*)(sX + kk * 128 + tg * 4);
            const float* wr = sW + (h * 32 + kk) * 64 + ds;
            ulonglong2 w01 = *(const ulonglong2*)(wr);
            ulonglong2 w23 = *(const ulonglong2*)(wr + 4);
            u64t bw[4] = {w01.x, w01.y, w23.x, w23.y};
            u64t av[4] = {bc2(a4.x), bc2(a4.y), bc2(a4.z), bc2(a4.w)};
#pragma unroll
            for (int i = 0; i < 4; i++)
#pragma unroll
                for (int j = 0; j < 4; j++) fma2(accX[i][j], av[i], bw[j]);
        }
        __syncthreads();
    }

    // write X (transposed, swizzled) over H region; stage WK into sW
#pragma unroll
    for (int j2 = 0; j2 < 4; j2++) {
        int d0 = ds + 2 * j2, d1 = d0 + 1;
        float c0 = sC[d0], c1 = sC[d1];
        float2 u0 = up2(accX[0][j2]), u1 = up2(accX[1][j2]);
        float2 u2 = up2(accX[2][j2]), u3 = up2(accX[3][j2]);
        *(float4*)(sX + d0 * 128 + SWZ(tg, d0) * 4) =
            make_float4(u0.x + c0, u1.x + c0, u2.x + c0, u3.x + c0);
        *(float4*)(sX + d1 * 128 + SWZ(tg, d1) * 4) =
            make_float4(u0.y + c1, u1.y + c1, u2.y + c1, u3.y + c1);
    }
    for (int i = tid; i < 4096; i += 256) sW[i] = wk[i];
    __syncthreads();

    const int gT   = tok0 + tg * 4;
    const int b    = gT >> perShift;
    const int lp   = gT & ((1 << perShift) - 1);
    const int slot = slotBase + lp;

    // K projection pass
    {
        u64t aK[4][4];
#pragma unroll
        for (int i = 0; i < 4; i++)
#pragma unroll
            for (int j = 0; j < 4; j++) aK[i][j] = 0ULL;
#pragma unroll 4
        for (int k = 0; k < 64; k++) {
            float4 a4 = *(const float4*)(sX + k * 128 + SWZ(tg, k) * 4);
            const float* kr = sW + k * 64 + ds;
            ulonglong2 k01 = *(const ulonglong2*)(kr);
            ulonglong2 k23 = *(const ulonglong2*)(kr + 4);
            u64t kw[4] = {k01.x, k01.y, k23.x, k23.y};
            u64t av[4] = {bc2(a4.x), bc2(a4.y), bc2(a4.z), bc2(a4.w)};
#pragma unroll
            for (int i = 0; i < 4; i++)
#pragma unroll
                for (int j = 0; j < 4; j++) fma2(aK[i][j], av[i], kw[j]);
        }
#pragma unroll
        for (int j2 = 0; j2 < 4; j2++) {
            int d0 = ds + 2 * j2, d1 = d0 + 1;
            float b0 = sBK[d0], b1v = sBK[d1];
            float2 u0 = up2(aK[0][j2]), u1 = up2(aK[1][j2]);
            float2 u2 = up2(aK[2][j2]), u3 = up2(aK[3][j2]);
            *(float4*)(g_KT + (b * 64 + d0) * 176 + slot) =
                make_float4(u0.x + b0, u1.x + b0, u2.x + b0, u3.x + b0);
            *(float4*)(g_KT + (b * 64 + d1) * 176 + slot) =
                make_float4(u0.y + b1v, u1.y + b1v, u2.y + b1v, u3.y + b1v);
        }
    }
    __syncthreads();
    for (int i = tid; i < 4096; i += 256) sW[i] = wv[i];
    __syncthreads();

    // V projection pass
    {
        u64t aV[4][4];
#pragma unroll
        for (int i = 0; i < 4; i++)
#pragma unroll
            for (int j = 0; j < 4; j++) aV[i][j] = 0ULL;
#pragma unroll 4
        for (int k = 0; k < 64; k++) {
            float4 a4 = *(const float4*)(sX + k * 128 + SWZ(tg, k) * 4);
            const float* vr = sW + k * 64 + ds;
            ulonglong2 v01 = *(const ulonglong2*)(vr);
            ulonglong2 v23 = *(const ulonglong2*)(vr + 4);
            u64t vw[4] = {v01.x, v01.y, v23.x, v23.y};
            u64t av[4] = {bc2(a4.x), bc2(a4.y), bc2(a4.z), bc2(a4.w)};
#pragma unroll
            for (int i = 0; i < 4; i++)
#pragma unroll
                for (int j = 0; j < 4; j++) fma2(aV[i][j], av[i], vw[j]);
        }
#pragma unroll
        for (int i = 0; i < 4; i++) {
            int row = (b * 176 + slot + i) * 64;
            float2 v0 = up2(aV[i][0]), v1 = up2(aV[i][1]);
            float2 v2 = up2(aV[i][2]), v3 = up2(aV[i][3]);
            *(float4*)(g_V + row + ds) =
                make_float4(v0.x + sBV[ds], v0.y + sBV[ds + 1], v1.x + sBV[ds + 2], v1.y + sBV[ds + 3]);
            *(float4*)(g_V + row + ds + 4) =
                make_float4(v2.x + sBV[ds + 4], v2.y + sBV[ds + 5], v3.x + sBV[ds + 6], v3.y + sBV[ds + 7]);
        }
    }

    if (type == 1) {
        __syncthreads();
        for (int i = tid; i < 4096; i += 256) sW[i] = wq[i];
        __syncthreads();
        u64t aQ[4][4];
#pragma unroll
        for (int i = 0; i < 4; i++)
#pragma unroll
            for (int j = 0; j < 4; j++) aQ[i][j] = 0ULL;
#pragma unroll 4
        for (int k = 0; k < 64; k++) {
            float4 a4 = *(const float4*)(sX + k * 128 + SWZ(tg, k) * 4);
            const float* qr = sW + k * 64 + ds;
            ulonglong2 q01 = *(const ulonglong2*)(qr);
            ulonglong2 q23 = *(const ulonglong2*)(qr + 4);
            u64t qw[4] = {q01.x, q01.y, q23.x, q23.y};
            u64t av[4] = {bc2(a4.x), bc2(a4.y), bc2(a4.z), bc2(a4.w)};
#pragma unroll
            for (int i = 0; i < 4; i++)
#pragma unroll
                for (int j = 0; j < 4; j++) fma2(aQ[i][j], av[i], qw[j]);
        }
#pragma unroll
        for (int j2 = 0; j2 < 4; j2++) {
            int d0 = ds + 2 * j2, d1 = d0 + 1;
            float b0 = sBQ[d0], b1v = sBQ[d1];
            float2 u0 = up2(aQ[0][j2]), u1 = up2(aQ[1][j2]);
            float2 u2 = up2(aQ[2][j2]), u3 = up2(aQ[3][j2]);
            *(float4*)(g_QT + (b * 64 + d0) * 128 + lp) =
                make_float4(u0.x + b0, u1.x + b0, u2.x + b0, u3.x + b0);
            *(float4*)(g_QT + (b * 64 + d1) * 128 + lp) =
                make_float4(u0.y + b1v, u1.y + b1v, u2.y + b1v, u3.y + b1v);
        }
    }
}

// ---------------------------------------------------------------------------
// head gemm: Out[d][64q] = act(A[64][64q] @ W[64][64] + bias); packed f32x2.
// ---------------------------------------------------------------------------
__device__ __forceinline__ void head_gemm64(
    const float* __restrict__ A, const float* __restrict__ W,
    const float* __restrict__ bias, float* __restrict__ Out,
    int qt, int dt, bool doRelu)
{
    u64t acc[4][2];
#pragma unroll
    for (int i = 0; i < 4; i++) { acc[i][0] = 0ULL; acc[i][1] = 0ULL; }
#pragma unroll 4
    for (int k = 0; k < 64; k++) {
        float4 a4 = *(const float4*)(A + k * 64 + ((qt ^ (k & 15)) << 2));
        ulonglong2 wv = *(const ulonglong2*)(W + k * 64 + dt * 4);
        u64t av[4] = {bc2(a4.x), bc2(a4.y), bc2(a4.z), bc2(a4.w)};
#pragma unroll
        for (int i = 0; i < 4; i++) {
            fma2(acc[i][0], av[i], wv.x);
            fma2(acc[i][1], av[i], wv.y);
        }
    }
    float2 u[4][2];
#pragma unroll
    for (int i = 0; i < 4; i++) { u[i][0] = up2(acc[i][0]); u[i][1] = up2(acc[i][1]); }
#pragma unroll
    for (int dj = 0; dj < 4; dj++) {
        int d = dt * 4 + dj;
        float bb = bias[d];
        float o0, o1, o2, o3;
        if (dj == 0)      { o0 = u[0][0].x; o1 = u[1][0].x; o2 = u[2][0].x; o3 = u[3][0].x; }
        else if (dj == 1) { o0 = u[0][0].y; o1 = u[1][0].y; o2 = u[2][0].y; o3 = u[3][0].y; }
        else if (dj == 2) { o0 = u[0][1].x; o1 = u[1][1].x; o2 = u[2][1].x; o3 = u[3][1].x; }
        else              { o0 = u[0][1].y; o1 = u[1][1].y; o2 = u[2][1].y; o3 = u[3][1].y; }
        o0 += bb; o1 += bb; o2 += bb; o3 += bb;
        if (doRelu) { o0 = fmaxf(o0, 0.f); o1 = fmaxf(o1, 0.f); o2 = fmaxf(o2, 0.f); o3 = fmaxf(o3, 0.f); }
        *(float4*)(Out + d * 64 + ((qt ^ (d & 15)) << 2)) = make_float4(o0, o1, o2, o3);
    }
}

// ---------------------------------------------------------------------------
// Kernel 2: attention + head. One CTA per (batch, query-half): grid 4096.
// ---------------------------------------------------------------------------
__global__ void __launch_bounds__(256, 2) attn_kernel(
    const float* __restrict__ pred_state, const float* __restrict__ prey_state,
    const float* __restrict__ obst_state, const void* __restrict__ alive,
    const float* __restrict__ w_pos,
    const float* __restrict__ wo,   const float* __restrict__ bo,
    const float* __restrict__ n_w1, const float* __restrict__ n_b1,
    const float* __restrict__ n_w2, const float* __restrict__ n_b2,
    const float* __restrict__ n_w3, const float* __restrict__ n_b3,
    float* __restrict__ out)
{
    extern __shared__ float sm[];
    float* sKV = sm;             // 12288: K [64][192] (GEMM1), then V [176][64];
                                 //        later X1 @0, n_w2 @4096
    float* sQT = sm + 12288;     // 4096:  Q [64][64], later X0
    float* sS  = sm + 16384;     // 11264: S [176][64] swz; later wo @0, n_w1 @4096
    float* sBK = sm + 27648;     // 176
    float* sMK = sm + 27824;     // 176
    float* sDQ = sm + 28000;     // 64
    float* sIv = sm + 28064;     // 64
    float* sBo = sm + 28128;     // 64
    float* sB1h= sm + 28192;     // 64
    float* sB2h= sm + 28256;     // 64
    float* sW3h= sm + 28320;     // 64
    float* sB3 = sm + 28384;     // 1   (alloc 28416)
    __shared__ int sFl[2];

    const int tid = threadIdx.x;
    const int b   = blockIdx.x >> 1;
    const int qh  = (blockIdx.x & 1) << 6;   // query-half offset

    if (tid == 0) { sFl[0] = 0; sFl[1] = 0; }
    __syncthreads();

    // phase 1: stage K, Q, small vectors; classify alive format
    {
        const float4* gk = (const float4*)(g_KT + b * 11264);
        for (int i = tid; i < 2816; i += 256) {          // K: 64 rows x 44 f4 -> stride 192
            int d = i / 44, c = i - d * 44;
            *(float4*)(sKV + d * 192 + c * 4) = gk[i];
        }
        for (int i = tid; i < 1024; i += 256) {          // Q half: 64 rows x 16 f4
            int d = i >> 4, c = i & 15;
            *(float4*)(sQT + d * 64 + c * 4) =
                *(const float4*)(g_QT + b * 8192 + d * 128 + qh + c * 4);
        }
        if (tid < 64) {
            sBo[tid]  = bo[tid];
            sB1h[tid] = n_b1[tid];
            sB2h[tid] = n_b2[tid];
            sW3h[tid] = n_w3[tid];
        }
        if (tid == 0) sB3[0] = n_b3[0];
        if (tid < 128) {
            unsigned int v = ((const unsigned int*)alive)[tid];
            if (v == 0x3F800000u) atomicOr(&sFl[0], 1);
            else if (v > 1u)      atomicOr(&sFl[1], 1);
        }
    }
    __syncthreads();
    const int fmt = sFl[0] ? 2 : (sFl[1] ? 0 : 1);

    // phase 2: per-key bias/mask; per-(local)query dead flag
    if (tid < NTOK) {
        int k = tid;
        float p0, p1, mk = 0.f;
        if (k < 16) {
            p0 = pred_state[(b * 16 + k) * 2];
            p1 = pred_state[(b * 16 + k) * 2 + 1];
        } else if (k < 144) {
            int j = k - 16;
            p0 = prey_state[(b * 128 + j) * 2];
            p1 = prey_state[(b * 128 + j) * 2 + 1];
            bool al;
            if (fmt == 0)      al = ((const unsigned char*)alive)[b * 128 + j] != 0;
            else if (fmt == 1) al = ((const int*)alive)[b * 128 + j] != 0;
            else               al = ((const float*)alive)[b * 128 + j] != 0.f;
            if (!al) mk = -1e9f;
        } else {
            int j = k - 144;
            p0 = obst_state[(b * 32 + j) * 3];
            p1 = obst_state[(b * 32 + j) * 3 + 1];
        }
        sBK[k] = p0 * w_pos[0] + p1 * w_pos[1];
        sMK[k] = mk;
    }
    if (tid < 64) {
        int q = qh + tid;
        bool al;
        if (fmt == 0)      al = ((const unsigned char*)alive)[b * 128 + q] != 0;
        else if (fmt == 1) al = ((const int*)alive)[b * 128 + q] != 0;
        else               al = ((const float*)alive)[b * 128 + q] != 0.f;
        sDQ[tid] = al ? 0.f : 1.f;
    }
    __syncthreads();

    // GEMM1: S[k][q] = (K.Q - bias_k)/8 + deadq*mask_k (packed over key pairs)
    {
        const int kg = tid >> 4, qg = tid & 15;   // 16x12 keys, 16x4 queries
        u64t acc[6][4];
#pragma unroll
        for (int p = 0; p < 6; p++)
#pragma unroll
            for (int j = 0; j < 4; j++) acc[p][j] = 0ULL;
#pragma unroll 4
        for (int d = 0; d < 64; d++) {
            const float* kr = sKV + d * 192 + kg * 12;
            ulonglong2 kA = *(const ulonglong2*)(kr);
            ulonglong2 kB = *(const ulonglong2*)(kr + 4);
            ulonglong2 kC = *(const ulonglong2*)(kr + 8);
            float4 q4 = *(const float4*)(sQT + d * 64 + qg * 4);
            u64t kp[6] = {kA.x, kA.y, kB.x, kB.y, kC.x, kC.y};
            u64t qb[4] = {bc2(q4.x), bc2(q4.y), bc2(q4.z), bc2(q4.w)};
#pragma unroll
            for (int p = 0; p < 6; p++)
#pragma unroll
                for (int j = 0; j < 4; j++) fma2(acc[p][j], kp[p], qb[j]);
        }
        float dq[4] = {sDQ[qg * 4], sDQ[qg * 4 + 1], sDQ[qg * 4 + 2], sDQ[qg * 4 + 3]};
#pragma unroll
        for (int p = 0; p < 6; p++) {
            int r0 = kg * 12 + 2 * p, r1 = r0 + 1;
            float2 u0 = up2(acc[p][0]), u1 = up2(acc[p][1]);
            float2 u2 = up2(acc[p][2]), u3 = up2(acc[p][3]);
            if (r0 < NTOK) {
                float bk = sBK[r0], mk = sMK[r0];
                *(float4*)(sS + r0 * 64 + ((qg ^ (r0 & 15)) << 2)) =
                    make_float4((u0.x - bk) * 0.125f + dq[0] * mk,
                                (u1.x - bk) * 0.125f + dq[1] * mk,
                                (u2.x - bk) * 0.125f + dq[2] * mk,
                                (u3.x - bk) * 0.125f + dq[3] * mk);
            }
            if (r1 < NTOK) {
                float bk = sBK[r1], mk = sMK[r1];
                *(float4*)(sS + r1 * 64 + ((qg ^ (r1 & 15)) << 2)) =
                    make_float4((u0.y - bk) * 0.125f + dq[0] * mk,
                                (u1.y - bk) * 0.125f + dq[1] * mk,
                                (u2.y - bk) * 0.125f + dq[2] * mk,
                                (u3.y - bk) * 0.125f + dq[3] * mk);
            }
        }
    }
    __syncthreads();

    // phase 4: stage V into sKV (K dead) + softmax over sS
    {
        const float4* gv = (const float4*)(g_V + b * 11264);
        float4* dv = (float4*)sKV;
        for (int i = tid; i < 2816; i += 256) dv[i] = gv[i];   // V [176][64]
    }
    {
        int q = tid >> 2, sub = tid & 3;
        int g = q >> 2, qr = q & 3;
        int k0 = sub * 44, k1 = k0 + 44;
        float m = -3.4e38f;
        for (int k = k0; k < k1; k++)
            m = fmaxf(m, sS[k * 64 + ((g ^ (k & 15)) << 2) + qr]);
        m = fmaxf(m, __shfl_xor_sync(0xFFFFFFFFu, m, 1));
        m = fmaxf(m, __shfl_xor_sync(0xFFFFFFFFu, m, 2));
        float ssum = 0.f;
        for (int k = k0; k < k1; k++) {
            int idx = k * 64 + ((g ^ (k & 15)) << 2) + qr;
            float p = __expf(sS[idx] - m);
            ssum += p;
            sS[idx] = p;
        }
        ssum += __shfl_xor_sync(0xFFFFFFFFu, ssum, 1);
        ssum += __shfl_xor_sync(0xFFFFFFFFu, ssum, 2);
        if (sub == 0) sIv[q] = 1.f / ssum;
    }
    __syncthreads();

    const int qt = tid & 15, dt = tid >> 4;
    float* sX0 = sQT;
    float* sX1 = sKV;            // after GEMM2, V dead
    float* sWo  = sS;
    float* sW1h = sS + 4096;
    float* sW2h = sKV + 4096;

    // GEMM2: X0[d][q] = (P @ V)[q][d] * iv[q]  (packed over d pairs)
    {
        u64t acc[4][2];
#pragma unroll
        for (int i = 0; i < 4; i++) { acc[i][0] = 0ULL; acc[i][1] = 0ULL; }
#pragma unroll 4
        for (int k = 0; k < NTOK; k++) {
            float4 p4 = *(const float4*)(sS + k * 64 + ((qt ^ (k & 15)) << 2));
            ulonglong2 vv = *(const ulonglong2*)(sKV + k * 64 + dt * 4);
            u64t pv[4] = {bc2(p4.x), bc2(p4.y), bc2(p4.z), bc2(p4.w)};
#pragma unroll
            for (int i = 0; i < 4; i++) {
                fma2(acc[i][0], pv[i], vv.x);
                fma2(acc[i][1], pv[i], vv.y);
            }
        }
        float iv[4] = {sIv[qt * 4], sIv[qt * 4 + 1], sIv[qt * 4 + 2], sIv[qt * 4 + 3]};
        float2 u[4][2];
#pragma unroll
        for (int i = 0; i < 4; i++) {
            u[i][0] = up2(acc[i][0]); u[i][1] = up2(acc[i][1]);
        }
        // X0 = sQT: Q reads finished at GEMM1 (synced since); safe to write now
#pragma unroll
        for (int dj = 0; dj < 4; dj++) {
            int d = dt * 4 + dj;
            float o0, o1, o2, o3;
            if (dj == 0)      { o0 = u[0][0].x; o1 = u[1][0].x; o2 = u[2][0].x; o3 = u[3][0].x; }
            else if (dj == 1) { o0 = u[0][0].y; o1 = u[1][0].y; o2 = u[2][0].y; o3 = u[3][0].y; }
            else if (dj == 2) { o0 = u[0][1].x; o1 = u[1][1].x; o2 = u[2][1].x; o3 = u[3][1].x; }
            else              { o0 = u[0][1].y; o1 = u[1][1].y; o2 = u[2][1].y; o3 = u[3][1].y; }
            *(float4*)(sX0 + d * 64 + ((qt ^ (d & 15)) << 2)) =
                make_float4(o0 * iv[0], o1 * iv[1], o2 * iv[2], o3 * iv[3]);
        }
    }
    __syncthreads();

    // stage head weights (sS and upper sKV are dead now)
    for (int i = tid; i < 4096; i += 256) {
        sWo[i]  = wo[i];
        sW1h[i] = n_w1[i];
        sW2h[i] = n_w2[i];
    }
    __syncthreads();

    head_gemm64(sX0, sWo,  sBo,  sX1, qt, dt, false);
    __syncthreads();
    head_gemm64(sX1, sW1h, sB1h, sX0, qt, dt, true);
    __syncthreads();
    head_gemm64(sX0, sW2h, sB2h, sX1, qt, dt, true);
    __syncthreads();

    // final: out[q] = tanh(X1[:,q] . n_w3 + b3); 4 threads per query
    {
        int q = tid >> 2, sub = tid & 3;
        int g = q >> 2, qr = q & 3;
        float a = 0.f;
#pragma unroll 4
        for (int dd = 0; dd < 16; dd++) {
            int d = sub * 16 + dd;
            a += sX1[d * 64 + ((g ^ (d & 15)) << 2) + qr] * sW3h[d];
        }
        a += __shfl_xor_sync(0xFFFFFFFFu, a, 1);
        a += __shfl_xor_sync(0xFFFFFFFFu, a, 2);
        if (sub == 0) out[b * 128 + qh + q] = tanhf(a + sB3[0]);
    }
}

// ---------------------------------------------------------------------------
extern "C" void kernel_launch(void* const* d_in, const int* in_sizes, int n_in,
                              void* d_out, int out_size)
{
    const float* pred  = (const float*)d_in[0];
    const float* prey  = (const float*)d_in[1];
    const float* obst  = (const float*)d_in[2];
    const void*  alive = d_in[3];
    const float* emb   = (const float*)d_in[4];
    const float* p_w1 = (const float*)d_in[5],  *p_b1 = (const float*)d_in[6];
    const float* p_w2 = (const float*)d_in[7],  *p_b2 = (const float*)d_in[8];
    const float* y_w1 = (const float*)d_in[9],  *y_b1 = (const float*)d_in[10];
    const float* y_w2 = (const float*)d_in[11], *y_b2 = (const float*)d_in[12];
    const float* o_w1 = (const float*)d_in[13], *o_b1 = (const float*)d_in[14];
    const float* o_w2 = (const float*)d_in[15], *o_b2 = (const float*)d_in[16];
    const float* wq = (const float*)d_in[17], *bq = (const float*)d_in[18];
    const float* wk = (const float*)d_in[19], *bk = (const float*)d_in[20];
    const float* wv = (const float*)d_in[21], *bv = (const float*)d_in[22];
    const float* wo = (const float*)d_in[23], *bo = (const float*)d_in[24];
    const float* w_pos = (const float*)d_in[25];
    const float* n_w1 = (const float*)d_in[26], *n_b1 = (const float*)d_in[27];
    const float* n_w2 = (const float*)d_in[28], *n_b2 = (const float*)d_in[29];
    const float* n_w3 = (const float*)d_in[30], *n_b3 = (const float*)d_in[31];
    float* out = (float*)d_out;

    cudaFuncSetAttribute(encode_kernel, cudaFuncAttributeMaxDynamicSharedMemorySize, 13248 * 4);
    cudaFuncSetAttribute(attn_kernel,   cudaFuncAttributeMaxDynamicSharedMemorySize, 28416 * 4);

    encode_kernel<<<2816, 256, 13248 * 4>>>(pred, prey, obst, emb,
        p_w1, p_b1, p_w2, p_b2, y_w1, y_b1, y_w2, y_b2, o_w1, o_b1, o_w2, o_b2,
        wq, bq, wk, bk, wv, bv);
    attn_kernel<<<4096, 256, 28416 * 4>>>(pred, prey, obst, alive, w_pos,
        wo, bo, n_w1, n_b1, n_w2, n_b2, n_w3, n_b3, out);
}

// round 6
// speedup vs baseline: 1.0066x; 1.0066x over previous
#include <cuda_runtime.h>
#include <math.h>

#define NB   2048
#define NTOK 176
#define NQ   128

// Scratch (allocation-free rule: device globals)
__device__ float g_KT[NB * 64 * NTOK];   // [b][d][k]
__device__ float g_V [NB * NTOK * 64];   // [b][k][d]
__device__ float g_QT[NB * 64 * NQ];     // [b][d][q]

#define SWZ(g, r) ((((g) ^ (r) ^ ((r) >> 3))) & 31)

// ---------------- packed f32x2 helpers (Blackwell FFMA2) -------------------
typedef unsigned long long u64t;
__device__ __forceinline__ void fma2(u64t& acc, u64t a, u64t b) {
    asm("fma.rn.f32x2 %0, %1, %2, %0;" : "+l"(acc) : "l"(a), "l"(b));
}
__device__ __forceinline__ u64t bc2(float x) {
    u64t r; unsigned int xi = __float_as_uint(x);
    asm("mov.b64 %0, {%1, %1};" : "=l"(r) : "r"(xi));
    return r;
}
__device__ __forceinline__ float2 up2(u64t v) {
    float2 r; asm("mov.b64 {%0, %1}, %2;" : "=f"(r.x), "=f"(r.y) : "l"(v));
    return r;
}

// ---------------------------------------------------------------------------
// Kernel 1: entity FFN encoders + K/V/Q projections.
// 2816 blocks x 256 threads; each block = 128 tokens of one entity type.
// Single weight buffer reloaded per phase (W2 -> WK -> WV -> WQ);
// H lives in the X buffer's first half. smem 53KB -> 3 CTAs/SM.
// ---------------------------------------------------------------------------
__global__ void __launch_bounds__(256, 3) encode_kernel(
    const float* __restrict__ pred_state, const float* __restrict__ prey_state,
    const float* __restrict__ obst_state, const float* __restrict__ emb,
    const float* __restrict__ p_w1, const float* __restrict__ p_b1,
    const float* __restrict__ p_w2, const float* __restrict__ p_b2,
    const float* __restrict__ y_w1, const float* __restrict__ y_b1,
    const float* __restrict__ y_w2, const float* __restrict__ y_b2,
    const float* __restrict__ o_w1, const float* __restrict__ o_b1,
    const float* __restrict__ o_w2, const float* __restrict__ o_b2,
    const float* __restrict__ wq, const float* __restrict__ bq,
    const float* __restrict__ wk, const float* __restrict__ bk,
    const float* __restrict__ wv, const float* __restrict__ bv)
{
    extern __shared__ float sm[];
    float* sW  = sm;            // 4096: W2, then WK, then WV, then WQ
    float* sX  = sm + 4096;     // 8192: H [32][128] in first half, then X [64][128] swz
    float* sC  = sm + 12288;    // 64
    float* sBK = sm + 12352;    // 64
    float* sBV = sm + 12416;    // 64
    float* sBQ = sm + 12480;    // 64
    float* sB1 = sm + 12544;    // 64
    float* sW1 = sm + 12608;    // 192
    float* sSt = sm + 12800;    // 384   (total 13184)

    const int tid = threadIdx.x;
    const int blk = blockIdx.x;

    int type, inDim, perShift, slotBase, tok0;
    const float *state, *w1, *b1, *w2;
    const float *b2;
    if (blk < 256)       { type = 0; tok0 = blk * 128;          state = pred_state; w1 = p_w1; b1 = p_b1; w2 = p_w2; b2 = p_b2; inDim = 2; perShift = 4; slotBase = 0;   }
    else if (blk < 2304) { type = 1; tok0 = (blk - 256)  * 128; state = prey_state; w1 = y_w1; b1 = y_b1; w2 = y_w2; b2 = y_b2; inDim = 2; perShift = 7; slotBase = 16;  }
    else                 { type = 2; tok0 = (blk - 2304) * 128; state = obst_state; w1 = o_w1; b1 = o_b1; w2 = o_w2; b2 = o_b2; inDim = 3; perShift = 5; slotBase = 144; }

    // phase 0: stage W2 + consts + states
    for (int i = tid; i < 4096; i += 256) sW[i] = w2[i];
    if (tid < 64) {
        sC[tid]  = b2[tid] + emb[type * 64 + tid];
        sBK[tid] = bk[tid];
        sBV[tid] = bv[tid];
        sBQ[tid] = bq[tid];
        sB1[tid] = b1[tid];
    }
    if (tid < inDim * 64) sW1[tid] = w1[tid];
    for (int i = tid; i < 128 * inDim; i += 256) {
        int t = i / inDim, j = i - t * inDim;
        sSt[t * 3 + j] = state[(tok0 + t) * inDim + j];
    }
    __syncthreads();

    const int dg = tid & 7, tg = tid >> 3, ds = dg * 8;

    // X = H @ W2 accumulated over two 32-k halves (H uses sX[0:4096])
    u64t accX[4][4];
#pragma unroll
    for (int i = 0; i < 4; i++)
#pragma unroll
        for (int j = 0; j < 4; j++) accX[i][j] = 0ULL;

#pragma unroll 1
    for (int h = 0; h < 2; h++) {
        for (int e = tid; e < 4096; e += 256) {
            int k = e >> 7, t = e & 127;
            int gk = h * 32 + k;
            float a = sB1[gk];
            for (int j = 0; j < inDim; j++) a += sSt[t * 3 + j] * sW1[j * 64 + gk];
            sX[k * 128 + t] = fmaxf(a, 0.f);
        }
        __syncthreads();
#pragma unroll 4
        for (int kk = 0; kk < 32; kk++) {
            float4 a4 = *(const float4*)(sX + kk * 128 + tg * 4);
            const float* wr = sW + (h * 32 + kk) * 64 + ds;
            ulonglong2 w01 = *(const ulonglong2*)(wr);
            ulonglong2 w23 = *(const ulonglong2*)(wr + 4);
            u64t bw[4] = {w01.x, w01.y, w23.x, w23.y};
            u64t av[4] = {bc2(a4.x), bc2(a4.y), bc2(a4.z), bc2(a4.w)};
#pragma unroll
            for (int i = 0; i < 4; i++)
#pragma unroll
                for (int j = 0; j < 4; j++) fma2(accX[i][j], av[i], bw[j]);
        }
        __syncthreads();
    }

    // write X (transposed, swizzled) over H region; stage WK into sW
#pragma unroll
    for (int j2 = 0; j2 < 4; j2++) {
        int d0 = ds + 2 * j2, d1 = d0 + 1;
        float c0 = sC[d0], c1 = sC[d1];
        float2 u0 = up2(accX[0][j2]), u1 = up2(accX[1][j2]);
        float2 u2 = up2(accX[2][j2]), u3 = up2(accX[3][j2]);
        *(float4*)(sX + d0 * 128 + SWZ(tg, d0) * 4) =
            make_float4(u0.x + c0, u1.x + c0, u2.x + c0, u3.x + c0);
        *(float4*)(sX + d1 * 128 + SWZ(tg, d1) * 4) =
            make_float4(u0.y + c1, u1.y + c1, u2.y + c1, u3.y + c1);
    }
    for (int i = tid; i < 4096; i += 256) sW[i] = wk[i];
    __syncthreads();

    const int gT   = tok0 + tg * 4;
    const int b    = gT >> perShift;
    const int lp   = gT & ((1 << perShift) - 1);
    const int slot = slotBase + lp;

    // K projection pass
    {
        u64t aK[4][4];
#pragma unroll
        for (int i = 0; i < 4; i++)
#pragma unroll
            for (int j = 0; j < 4; j++) aK[i][j] = 0ULL;
#pragma unroll 4
        for (int k = 0; k < 64; k++) {
            float4 a4 = *(const float4*)(sX + k * 128 + SWZ(tg, k) * 4);
            const float* kr = sW + k * 64 + ds;
            ulonglong2 k01 = *(const ulonglong2*)(kr);
            ulonglong2 k23 = *(const ulonglong2*)(kr + 4);
            u64t kw[4] = {k01.x, k01.y, k23.x, k23.y};
            u64t av[4] = {bc2(a4.x), bc2(a4.y), bc2(a4.z), bc2(a4.w)};
#pragma unroll
            for (int i = 0; i < 4; i++)
#pragma unroll
                for (int j = 0; j < 4; j++) fma2(aK[i][j], av[i], kw[j]);
        }
#pragma unroll
        for (int j2 = 0; j2 < 4; j2++) {
            int d0 = ds + 2 * j2, d1 = d0 + 1;
            float b0 = sBK[d0], b1v = sBK[d1];
            float2 u0 = up2(aK[0][j2]), u1 = up2(aK[1][j2]);
            float2 u2 = up2(aK[2][j2]), u3 = up2(aK[3][j2]);
            *(float4*)(g_KT + (b * 64 + d0) * 176 + slot) =
                make_float4(u0.x + b0, u1.x + b0, u2.x + b0, u3.x + b0);
            *(float4*)(g_KT + (b * 64 + d1) * 176 + slot) =
                make_float4(u0.y + b1v, u1.y + b1v, u2.y + b1v, u3.y + b1v);
        }
    }
    __syncthreads();
    for (int i = tid; i < 4096; i += 256) sW[i] = wv[i];
    __syncthreads();

    // V projection pass
    {
        u64t aV[4][4];
#pragma unroll
        for (int i = 0; i < 4; i++)
#pragma unroll
            for (int j = 0; j < 4; j++) aV[i][j] = 0ULL;
#pragma unroll 4
        for (int k = 0; k < 64; k++) {
            float4 a4 = *(const float4*)(sX + k * 128 + SWZ(tg, k) * 4);
            const float* vr = sW + k * 64 + ds;
            ulonglong2 v01 = *(const ulonglong2*)(vr);
            ulonglong2 v23 = *(const ulonglong2*)(vr + 4);
            u64t vw[4] = {v01.x, v01.y, v23.x, v23.y};
            u64t av[4] = {bc2(a4.x), bc2(a4.y), bc2(a4.z), bc2(a4.w)};
#pragma unroll
            for (int i = 0; i < 4; i++)
#pragma unroll
                for (int j = 0; j < 4; j++) fma2(aV[i][j], av[i], vw[j]);
        }
#pragma unroll
        for (int i = 0; i < 4; i++) {
            int row = (b * 176 + slot + i) * 64;
            float2 v0 = up2(aV[i][0]), v1 = up2(aV[i][1]);
            float2 v2 = up2(aV[i][2]), v3 = up2(aV[i][3]);
            *(float4*)(g_V + row + ds) =
                make_float4(v0.x + sBV[ds], v0.y + sBV[ds + 1], v1.x + sBV[ds + 2], v1.y + sBV[ds + 3]);
            *(float4*)(g_V + row + ds + 4) =
                make_float4(v2.x + sBV[ds + 4], v2.y + sBV[ds + 5], v3.x + sBV[ds + 6], v3.y + sBV[ds + 7]);
        }
    }

    if (type == 1) {
        __syncthreads();
        for (int i = tid; i < 4096; i += 256) sW[i] = wq[i];
        __syncthreads();
        u64t aQ[4][4];
#pragma unroll
        for (int i = 0; i < 4; i++)
#pragma unroll
            for (int j = 0; j < 4; j++) aQ[i][j] = 0ULL;
#pragma unroll 4
        for (int k = 0; k < 64; k++) {
            float4 a4 = *(const float4*)(sX + k * 128 + SWZ(tg, k) * 4);
            const float* qr = sW + k * 64 + ds;
            ulonglong2 q01 = *(const ulonglong2*)(qr);
            ulonglong2 q23 = *(const ulonglong2*)(qr + 4);
            u64t qw[4] = {q01.x, q01.y, q23.x, q23.y};
            u64t av[4] = {bc2(a4.x), bc2(a4.y), bc2(a4.z), bc2(a4.w)};
#pragma unroll
            for (int i = 0; i < 4; i++)
#pragma unroll
                for (int j = 0; j < 4; j++) fma2(aQ[i][j], av[i], qw[j]);
        }
#pragma unroll
        for (int j2 = 0; j2 < 4; j2++) {
            int d0 = ds + 2 * j2, d1 = d0 + 1;
            float b0 = sBQ[d0], b1v = sBQ[d1];
            float2 u0 = up2(aQ[0][j2]), u1 = up2(aQ[1][j2]);
            float2 u2 = up2(aQ[2][j2]), u3 = up2(aQ[3][j2]);
            *(float4*)(g_QT + (b * 64 + d0) * 128 + lp) =
                make_float4(u0.x + b0, u1.x + b0, u2.x + b0, u3.x + b0);
            *(float4*)(g_QT + (b * 64 + d1) * 128 + lp) =
                make_float4(u0.y + b1v, u1.y + b1v, u2.y + b1v, u3.y + b1v);
        }
    }
}

// ---------------------------------------------------------------------------
// head gemm: Out[d][64q] = act(A[64][64q] @ W[64][64] + bias); packed f32x2.
// ---------------------------------------------------------------------------
__device__ __forceinline__ void head_gemm64(
    const float* __restrict__ A, const float* __restrict__ W,
    const float* __restrict__ bias, float* __restrict__ Out,
    int qt, int dt, bool doRelu)
{
    u64t acc[4][2];
#pragma unroll
    for (int i = 0; i < 4; i++) { acc[i][0] = 0ULL; acc[i][1] = 0ULL; }
#pragma unroll 4
    for (int k = 0; k < 64; k++) {
        float4 a4 = *(const float4*)(A + k * 64 + ((qt ^ (k & 15)) << 2));
        ulonglong2 wv = *(const ulonglong2*)(W + k * 64 + dt * 4);
        u64t av[4] = {bc2(a4.x), bc2(a4.y), bc2(a4.z), bc2(a4.w)};
#pragma unroll
        for (int i = 0; i < 4; i++) {
            fma2(acc[i][0], av[i], wv.x);
            fma2(acc[i][1], av[i], wv.y);
        }
    }
    float2 u[4][2];
#pragma unroll
    for (int i = 0; i < 4; i++) { u[i][0] = up2(acc[i][0]); u[i][1] = up2(acc[i][1]); }
#pragma unroll
    for (int dj = 0; dj < 4; dj++) {
        int d = dt * 4 + dj;
        float bb = bias[d];
        float o0, o1, o2, o3;
        if (dj == 0)      { o0 = u[0][0].x; o1 = u[1][0].x; o2 = u[2][0].x; o3 = u[3][0].x; }
        else if (dj == 1) { o0 = u[0][0].y; o1 = u[1][0].y; o2 = u[2][0].y; o3 = u[3][0].y; }
        else if (dj == 2) { o0 = u[0][1].x; o1 = u[1][1].x; o2 = u[2][1].x; o3 = u[3][1].x; }
        else              { o0 = u[0][1].y; o1 = u[1][1].y; o2 = u[2][1].y; o3 = u[3][1].y; }
        o0 += bb; o1 += bb; o2 += bb; o3 += bb;
        if (doRelu) { o0 = fmaxf(o0, 0.f); o1 = fmaxf(o1, 0.f); o2 = fmaxf(o2, 0.f); o3 = fmaxf(o3, 0.f); }
        *(float4*)(Out + d * 64 + ((qt ^ (d & 15)) << 2)) = make_float4(o0, o1, o2, o3);
    }
}

// ---------------------------------------------------------------------------
// Kernel 2: attention + head. One CTA per (batch, query-half): grid 4096.
// ---------------------------------------------------------------------------
__global__ void __launch_bounds__(256, 2) attn_kernel(
    const float* __restrict__ pred_state, const float* __restrict__ prey_state,
    const float* __restrict__ obst_state, const void* __restrict__ alive,
    const float* __restrict__ w_pos,
    const float* __restrict__ wo,   const float* __restrict__ bo,
    const float* __restrict__ n_w1, const float* __restrict__ n_b1,
    const float* __restrict__ n_w2, const float* __restrict__ n_b2,
    const float* __restrict__ n_w3, const float* __restrict__ n_b3,
    float* __restrict__ out)
{
    extern __shared__ float sm[];
    float* sKV = sm;             // 12288: K [64][192] (GEMM1), then V [176][64];
                                 //        later X1 @0, n_w2 @4096
    float* sQT = sm + 12288;     // 4096:  Q [64][64], later X0
    float* sS  = sm + 16384;     // 11264: S [176][64] swz; later wo @0, n_w1 @4096
    float* sBK = sm + 27648;     // 176
    float* sMK = sm + 27824;     // 176
    float* sDQ = sm + 28000;     // 64
    float* sIv = sm + 28064;     // 64
    float* sBo = sm + 28128;     // 64
    float* sB1h= sm + 28192;     // 64
    float* sB2h= sm + 28256;     // 64
    float* sW3h= sm + 28320;     // 64
    float* sB3 = sm + 28384;     // 1   (alloc 28416)
    __shared__ int sFl[2];

    const int tid = threadIdx.x;
    const int b   = blockIdx.x >> 1;
    const int qh  = (blockIdx.x & 1) << 6;   // query-half offset

    if (tid == 0) { sFl[0] = 0; sFl[1] = 0; }
    __syncthreads();

    // phase 1: stage K, Q, small vectors; classify alive format
    {
        const float4* gk = (const float4*)(g_KT + b * 11264);
        for (int i = tid; i < 2816; i += 256) {          // K: 64 rows x 44 f4 -> stride 192
            int d = i / 44, c = i - d * 44;
            *(float4*)(sKV + d * 192 + c * 4) = gk[i];
        }
        for (int i = tid; i < 1024; i += 256) {          // Q half: 64 rows x 16 f4
            int d = i >> 4, c = i & 15;
            *(float4*)(sQT + d * 64 + c * 4) =
                *(const float4*)(g_QT + b * 8192 + d * 128 + qh + c * 4);
        }
        if (tid < 64) {
            sBo[tid]  = bo[tid];
            sB1h[tid] = n_b1[tid];
            sB2h[tid] = n_b2[tid];
            sW3h[tid] = n_w3[tid];
        }
        if (tid == 0) sB3[0] = n_b3[0];
        if (tid < 128) {
            unsigned int v = ((const unsigned int*)alive)[tid];
            if (v == 0x3F800000u) atomicOr(&sFl[0], 1);
            else if (v > 1u)      atomicOr(&sFl[1], 1);
        }
    }
    __syncthreads();
    const int fmt = sFl[0] ? 2 : (sFl[1] ? 0 : 1);

    // phase 2: per-key bias/mask; per-(local)query dead flag
    if (tid < NTOK) {
        int k = tid;
        float p0, p1, mk = 0.f;
        if (k < 16) {
            p0 = pred_state[(b * 16 + k) * 2];
            p1 = pred_state[(b * 16 + k) * 2 + 1];
        } else if (k < 144) {
            int j = k - 16;
            p0 = prey_state[(b * 128 + j) * 2];
            p1 = prey_state[(b * 128 + j) * 2 + 1];
            bool al;
            if (fmt == 0)      al = ((const unsigned char*)alive)[b * 128 + j] != 0;
            else if (fmt == 1) al = ((const int*)alive)[b * 128 + j] != 0;
            else               al = ((const float*)alive)[b * 128 + j] != 0.f;
            if (!al) mk = -1e9f;
        } else {
            int j = k - 144;
            p0 = obst_state[(b * 32 + j) * 3];
            p1 = obst_state[(b * 32 + j) * 3 + 1];
        }
        sBK[k] = p0 * w_pos[0] + p1 * w_pos[1];
        sMK[k] = mk;
    }
    if (tid < 64) {
        int q = qh + tid;
        bool al;
        if (fmt == 0)      al = ((const unsigned char*)alive)[b * 128 + q] != 0;
        else if (fmt == 1) al = ((const int*)alive)[b * 128 + q] != 0;
        else               al = ((const float*)alive)[b * 128 + q] != 0.f;
        sDQ[tid] = al ? 0.f : 1.f;
    }
    __syncthreads();

    // GEMM1: S[k][q] = (K.Q - bias_k)/8 + deadq*mask_k (packed over key pairs)
    {
        const int kg = tid >> 4, qg = tid & 15;   // 16x12 keys, 16x4 queries
        u64t acc[6][4];
#pragma unroll
        for (int p = 0; p < 6; p++)
#pragma unroll
            for (int j = 0; j < 4; j++) acc[p][j] = 0ULL;
#pragma unroll 4
        for (int d = 0; d < 64; d++) {
            const float* kr = sKV + d * 192 + kg * 12;
            ulonglong2 kA = *(const ulonglong2*)(kr);
            ulonglong2 kB = *(const ulonglong2*)(kr + 4);
            ulonglong2 kC = *(const ulonglong2*)(kr + 8);
            float4 q4 = *(const float4*)(sQT + d * 64 + qg * 4);
            u64t kp[6] = {kA.x, kA.y, kB.x, kB.y, kC.x, kC.y};
            u64t qb[4] = {bc2(q4.x), bc2(q4.y), bc2(q4.z), bc2(q4.w)};
#pragma unroll
            for (int p = 0; p < 6; p++)
#pragma unroll
                for (int j = 0; j < 4; j++) fma2(acc[p][j], kp[p], qb[j]);
        }
        float dq[4] = {sDQ[qg * 4], sDQ[qg * 4 + 1], sDQ[qg * 4 + 2], sDQ[qg * 4 + 3]};
#pragma unroll
        for (int p = 0; p < 6; p++) {
            int r0 = kg * 12 + 2 * p, r1 = r0 + 1;
            float2 u0 = up2(acc[p][0]), u1 = up2(acc[p][1]);
            float2 u2 = up2(acc[p][2]), u3 = up2(acc[p][3]);
            if (r0 < NTOK) {
                float bk = sBK[r0], mk = sMK[r0];
                *(float4*)(sS + r0 * 64 + ((qg ^ (r0 & 15)) << 2)) =
                    make_float4((u0.x - bk) * 0.125f + dq[0] * mk,
                                (u1.x - bk) * 0.125f + dq[1] * mk,
                                (u2.x - bk) * 0.125f + dq[2] * mk,
                                (u3.x - bk) * 0.125f + dq[3] * mk);
            }
            if (r1 < NTOK) {
                float bk = sBK[r1], mk = sMK[r1];
                *(float4*)(sS + r1 * 64 + ((qg ^ (r1 & 15)) << 2)) =
                    make_float4((u0.y - bk) * 0.125f + dq[0] * mk,
                                (u1.y - bk) * 0.125f + dq[1] * mk,
                                (u2.y - bk) * 0.125f + dq[2] * mk,
                                (u3.y - bk) * 0.125f + dq[3] * mk);
            }
        }
    }
    __syncthreads();

    // phase 4: stage V into sKV (K dead) + softmax over sS
    {
        const float4* gv = (const float4*)(g_V + b * 11264);
        float4* dv = (float4*)sKV;
        for (int i = tid; i < 2816; i += 256) dv[i] = gv[i];   // V [176][64]
    }
    {
        int q = tid >> 2, sub = tid & 3;
        int g = q >> 2, qr = q & 3;
        int k0 = sub * 44, k1 = k0 + 44;
        float m = -3.4e38f;
        for (int k = k0; k < k1; k++)
            m = fmaxf(m, sS[k * 64 + ((g ^ (k & 15)) << 2) + qr]);
        m = fmaxf(m, __shfl_xor_sync(0xFFFFFFFFu, m, 1));
        m = fmaxf(m, __shfl_xor_sync(0xFFFFFFFFu, m, 2));
        float ssum = 0.f;
        for (int k = k0; k < k1; k++) {
            int idx = k * 64 + ((g ^ (k & 15)) << 2) + qr;
            float p = __expf(sS[idx] - m);
            ssum += p;
            sS[idx] = p;
        }
        ssum += __shfl_xor_sync(0xFFFFFFFFu, ssum, 1);
        ssum += __shfl_xor_sync(0xFFFFFFFFu, ssum, 2);
        if (sub == 0) sIv[q] = 1.f / ssum;
    }
    __syncthreads();

    const int qt = tid & 15, dt = tid >> 4;
    float* sX0 = sQT;
    float* sX1 = sKV;            // after GEMM2, V dead
    float* sWo  = sS;
    float* sW1h = sS + 4096;
    float* sW2h = sKV + 4096;

    // GEMM2: X0[d][q] = (P @ V)[q][d] * iv[q]  (packed over d pairs)
    {
        u64t acc[4][2];
#pragma unroll
        for (int i = 0; i < 4; i++) { acc[i][0] = 0ULL; acc[i][1] = 0ULL; }
#pragma unroll 4
        for (int k = 0; k < NTOK; k++) {
            float4 p4 = *(const float4*)(sS + k * 64 + ((qt ^ (k & 15)) << 2));
            ulonglong2 vv = *(const ulonglong2*)(sKV + k * 64 + dt * 4);
            u64t pv[4] = {bc2(p4.x), bc2(p4.y), bc2(p4.z), bc2(p4.w)};
#pragma unroll
            for (int i = 0; i < 4; i++) {
                fma2(acc[i][0], pv[i], vv.x);
                fma2(acc[i][1], pv[i], vv.y);
            }
        }
        float iv[4] = {sIv[qt * 4], sIv[qt * 4 + 1], sIv[qt * 4 + 2], sIv[qt * 4 + 3]};
        float2 u[4][2];
#pragma unroll
        for (int i = 0; i < 4; i++) {
            u[i][0] = up2(acc[i][0]); u[i][1] = up2(acc[i][1]);
        }
        // X0 = sQT: Q reads finished at GEMM1 (synced since); safe to write now
#pragma unroll
        for (int dj = 0; dj < 4; dj++) {
            int d = dt * 4 + dj;
            float o0, o1, o2, o3;
            if (dj == 0)      { o0 = u[0][0].x; o1 = u[1][0].x; o2 = u[2][0].x; o3 = u[3][0].x; }
            else if (dj == 1) { o0 = u[0][0].y; o1 = u[1][0].y; o2 = u[2][0].y; o3 = u[3][0].y; }
            else if (dj == 2) { o0 = u[0][1].x; o1 = u[1][1].x; o2 = u[2][1].x; o3 = u[3][1].x; }
            else              { o0 = u[0][1].y; o1 = u[1][1].y; o2 = u[2][1].y; o3 = u[3][1].y; }
            *(float4*)(sX0 + d * 64 + ((qt ^ (d & 15)) << 2)) =
                make_float4(o0 * iv[0], o1 * iv[1], o2 * iv[2], o3 * iv[3]);
        }
    }
    __syncthreads();

    // stage head weights (sS and upper sKV are dead now)
    for (int i = tid; i < 4096; i += 256) {
        sWo[i]  = wo[i];
        sW1h[i] = n_w1[i];
        sW2h[i] = n_w2[i];
    }
    __syncthreads();

    head_gemm64(sX0, sWo,  sBo,  sX1, qt, dt, false);
    __syncthreads();
    head_gemm64(sX1, sW1h, sB1h, sX0, qt, dt, true);
    __syncthreads();
    head_gemm64(sX0, sW2h, sB2h, sX1, qt, dt, true);
    __syncthreads();

    // final: out[q] = tanh(X1[:,q] . n_w3 + b3); 4 threads per query
    {
        int q = tid >> 2, sub = tid & 3;
        int g = q >> 2, qr = q & 3;
        float a = 0.f;
#pragma unroll 4
        for (int dd = 0; dd < 16; dd++) {
            int d = sub * 16 + dd;
            a += sX1[d * 64 + ((g ^ (d & 15)) << 2) + qr] * sW3h[d];
        }
        a += __shfl_xor_sync(0xFFFFFFFFu, a, 1);
        a += __shfl_xor_sync(0xFFFFFFFFu, a, 2);
        if (sub == 0) out[b * 128 + qh + q] = tanhf(a + sB3[0]);
    }
}

// ---------------------------------------------------------------------------
extern "C" void kernel_launch(void* const* d_in, const int* in_sizes, int n_in,
                              void* d_out, int out_size)
{
    const float* pred  = (const float*)d_in[0];
    const float* prey  = (const float*)d_in[1];
    const float* obst  = (const float*)d_in[2];
    const void*  alive = d_in[3];
    const float* emb   = (const float*)d_in[4];
    const float* p_w1 = (const float*)d_in[5],  *p_b1 = (const float*)d_in[6];
    const float* p_w2 = (const float*)d_in[7],  *p_b2 = (const float*)d_in[8];
    const float* y_w1 = (const float*)d_in[9],  *y_b1 = (const float*)d_in[10];
    const float* y_w2 = (const float*)d_in[11], *y_b2 = (const float*)d_in[12];
    const float* o_w1 = (const float*)d_in[13], *o_b1 = (const float*)d_in[14];
    const float* o_w2 = (const float*)d_in[15], *o_b2 = (const float*)d_in[16];
    const float* wq = (const float*)d_in[17], *bq = (const float*)d_in[18];
    const float* wk = (const float*)d_in[19], *bk = (const float*)d_in[20];
    const float* wv = (const float*)d_in[21], *bv = (const float*)d_in[22];
    const float* wo = (const float*)d_in[23], *bo = (const float*)d_in[24];
    const float* w_pos = (const float*)d_in[25];
    const float* n_w1 = (const float*)d_in[26], *n_b1 = (const float*)d_in[27];
    const float* n_w2 = (const float*)d_in[28], *n_b2 = (const float*)d_in[29];
    const float* n_w3 = (const float*)d_in[30], *n_b3 = (const float*)d_in[31];
    float* out = (float*)d_out;

    cudaFuncSetAttribute(encode_kernel, cudaFuncAttributeMaxDynamicSharedMemorySize, 13248 * 4);
    cudaFuncSetAttribute(attn_kernel,   cudaFuncAttributeMaxDynamicSharedMemorySize, 28416 * 4);

    encode_kernel<<<2816, 256, 13248 * 4>>>(pred, prey, obst, emb,
        p_w1, p_b1, p_w2, p_b2, y_w1, y_b1, y_w2, y_b2, o_w1, o_b1, o_w2, o_b2,
        wq, bq, wk, bk, wv, bv);
    attn_kernel<<<4096, 256, 28416 * 4>>>(pred, prey, obst, alive, w_pos,
        wo, bo, n_w1, n_b1, n_w2, n_b2, n_w3, n_b3, out);
}